// round 3
// baseline (speedup 1.0000x reference)
#include <cuda_runtime.h>

#define NN 50000
#define EE 800000
#define HH 128
#define K2 256
#define BM 128
#define BK 16
#define NPB 32

// ------------------------- device scratch (no allocations allowed) ----------
__device__ int   g_rowptr[NN + 1];
__device__ int   g_cursor[NN];
__device__ int   g_csr[EE];
__device__ float g_feat[NN * K2];     // per-layer concat [mean | x]
__device__ float g_h0[NN * HH];
__device__ float g_h1[NN * HH];
__device__ float g_wcatT[K2 * HH];    // [Wl | Wr] transposed: k-major

// ------------------------- f32x2 helpers ------------------------------------
__device__ __forceinline__ unsigned long long pk2(float lo, float hi) {
    unsigned long long r;
    asm("mov.b64 %0, {%1, %2};" : "=l"(r) : "f"(lo), "f"(hi));
    return r;
}
__device__ __forceinline__ void upk2(unsigned long long v, float& lo, float& hi) {
    asm("mov.b64 {%0, %1}, %2;" : "=f"(lo), "=f"(hi) : "l"(v));
}
__device__ __forceinline__ void fma2(unsigned long long& d, unsigned long long a, unsigned long long b) {
    asm("fma.rn.f32x2 %0, %1, %2, %3;" : "=l"(d) : "l"(a), "l"(b), "l"(d));
}

// ------------------------- CSR build ----------------------------------------
__global__ void k_zero_counts() {
    int i = blockIdx.x * blockDim.x + threadIdx.x;
    if (i <= NN) g_rowptr[i] = 0;
}

__global__ void k_count(const int* __restrict__ dst) {
    int e = blockIdx.x * blockDim.x + threadIdx.x;
    if (e < EE) atomicAdd(&g_rowptr[dst[e]], 1);
}

__global__ void k_scan() {
    __shared__ int s[1024];
    int t = threadIdx.x;
    const int chunk = (NN + 1023) / 1024;
    int b = t * chunk;
    int e = b + chunk;
    if (e > NN) e = NN;
    int sum = 0;
    for (int i = b; i < e; i++) sum += g_rowptr[i];
    s[t] = sum;
    __syncthreads();
    for (int off = 1; off < 1024; off <<= 1) {
        int v = (t >= off) ? s[t - off] : 0;
        __syncthreads();
        s[t] += v;
        __syncthreads();
    }
    int run = (t == 0) ? 0 : s[t - 1];
    for (int i = b; i < e; i++) {
        int c = g_rowptr[i];
        g_rowptr[i] = run;
        g_cursor[i] = run;
        run += c;
    }
    if (t == 0) g_rowptr[NN] = EE;
}

__global__ void k_fill(const int* __restrict__ src, const int* __restrict__ dst) {
    int e = blockIdx.x * blockDim.x + threadIdx.x;
    if (e < EE) {
        int d = dst[e];
        int pos = atomicAdd(&g_cursor[d], 1);
        g_csr[pos] = src[e];
    }
}

// ------------------------- aggregation: warp per node -----------------------
// src_sel: 0 = external x, 1 = g_h0, 2 = g_h1
// writes g_feat[node][0:128] = mean of neighbors, g_feat[node][128:256] = own row
__global__ void k_aggregate(const float* __restrict__ xext, int src_sel) {
    const float* xin = (src_sel == 0) ? xext : ((src_sel == 1) ? (const float*)g_h0 : (const float*)g_h1);
    int gt = blockIdx.x * blockDim.x + threadIdx.x;
    int node = gt >> 5;
    int lane = gt & 31;
    if (node >= NN) return;
    int s0 = g_rowptr[node], s1 = g_rowptr[node + 1];
    const float4* x4 = (const float4*)xin;
    float4 a0 = make_float4(0.f, 0.f, 0.f, 0.f);
    float4 a1 = a0;
    int i = s0;
    for (; i + 2 <= s1; i += 2) {
        int p = g_csr[i];
        int q = g_csr[i + 1];
        float4 v = x4[p * 32 + lane];
        float4 w = x4[q * 32 + lane];
        a0.x += v.x; a0.y += v.y; a0.z += v.z; a0.w += v.w;
        a1.x += w.x; a1.y += w.y; a1.z += w.z; a1.w += w.w;
    }
    if (i < s1) {
        int p = g_csr[i];
        float4 v = x4[p * 32 + lane];
        a0.x += v.x; a0.y += v.y; a0.z += v.z; a0.w += v.w;
    }
    float inv = 1.f / fmaxf((float)(s1 - s0), 1.f);
    float4 m;
    m.x = (a0.x + a1.x) * inv;
    m.y = (a0.y + a1.y) * inv;
    m.z = (a0.z + a1.z) * inv;
    m.w = (a0.w + a1.w) * inv;
    float4 own = x4[node * 32 + lane];
    float4* f4 = (float4*)g_feat;
    f4[node * 64 + lane]      = m;
    f4[node * 64 + 32 + lane] = own;
}

// ------------------------- weight concat/transpose --------------------------
// g_wcatT[k][j]: k<128 -> Wl[j][k], else Wr[j][k-128]
__global__ void k_prep(const float* __restrict__ Wl, const float* __restrict__ Wr) {
    int idx = blockIdx.x * blockDim.x + threadIdx.x;
    if (idx < K2 * HH) {
        int k = idx >> 7;
        int j = idx & 127;
        g_wcatT[idx] = (k < HH) ? Wl[j * HH + k] : Wr[j * HH + (k - HH)];
    }
}

// ------------------------- fused SGEMM + bias + relu (f32x2) -----------------
// out_sel: 1 = g_h0, 2 = g_h1
// out[M=NN, 128] = relu(g_feat[NN,256] @ g_wcatT[256,128] + bias)
__global__ void __launch_bounds__(256, 2) k_gemm(const float* __restrict__ bias,
                                                 int out_sel) {
    float* out = (out_sel == 1) ? (float*)g_h0 : (float*)g_h1;
    __shared__ unsigned long long As2[BK][BM + 1];  // A duplicated: {a,a} pairs
    __shared__ float Bs[BK][HH];

    int tid = threadIdx.x;
    int blockRow = blockIdx.x * BM;
    const float4* feat4 = (const float4*)g_feat;
    const float4* b4 = (const float4*)g_wcatT;

    unsigned long long acc[8][4];
#pragma unroll
    for (int i = 0; i < 8; i++)
#pragma unroll
        for (int j = 0; j < 4; j++) acc[i][j] = 0ull;

    int tx = tid & 15, ty = tid >> 4;

    for (int k0 = 0; k0 < K2; k0 += BK) {
        // load A tile (128 rows x 16 k), store duplicated & k-major
#pragma unroll
        for (int t = 0; t < 2; t++) {
            int idx = tid + t * 256;      // 0..511
            int row = idx >> 2;           // 0..127
            int k4 = idx & 3;             // float4 within the BK slab
            int grow = blockRow + row;
            float4 v = make_float4(0.f, 0.f, 0.f, 0.f);
            if (grow < NN) v = feat4[grow * 64 + (k0 >> 2) + k4];
            int kk = k4 * 4;
            As2[kk + 0][row] = pk2(v.x, v.x);
            As2[kk + 1][row] = pk2(v.y, v.y);
            As2[kk + 2][row] = pk2(v.z, v.z);
            As2[kk + 3][row] = pk2(v.w, v.w);
        }
        // load B tile (16 k x 128 cols)
#pragma unroll
        for (int t = 0; t < 2; t++) {
            int idx = tid + t * 256;
            int k = idx >> 5;
            int c4 = idx & 31;
            float4 v = b4[(k0 + k) * 32 + c4];
            *(float4*)&Bs[k][c4 * 4] = v;
        }
        __syncthreads();

#pragma unroll
        for (int kk = 0; kk < BK; kk++) {
            float4 b0 = *(const float4*)&Bs[kk][tx * 8];
            float4 b1 = *(const float4*)&Bs[kk][tx * 8 + 4];
            unsigned long long bb0 = pk2(b0.x, b0.y);
            unsigned long long bb1 = pk2(b0.z, b0.w);
            unsigned long long bb2 = pk2(b1.x, b1.y);
            unsigned long long bb3 = pk2(b1.z, b1.w);
#pragma unroll
            for (int i = 0; i < 8; i++) {
                unsigned long long aa = As2[kk][ty * 8 + i];
                fma2(acc[i][0], aa, bb0);
                fma2(acc[i][1], aa, bb1);
                fma2(acc[i][2], aa, bb2);
                fma2(acc[i][3], aa, bb3);
            }
        }
        __syncthreads();
    }

    // epilogue: bias + relu, float2 stores
#pragma unroll
    for (int i = 0; i < 8; i++) {
        int grow = blockRow + ty * 8 + i;
        if (grow < NN) {
#pragma unroll
            for (int j4 = 0; j4 < 4; j4++) {
                int col = tx * 8 + j4 * 2;
                float lo, hi;
                upk2(acc[i][j4], lo, hi);
                float2 o;
                o.x = fmaxf(lo + bias[col], 0.f);
                o.y = fmaxf(hi + bias[col + 1], 0.f);
                *(float2*)&out[grow * HH + col] = o;
            }
        }
    }
}

// ------------------------- fused head MLP -----------------------------------
// out[n] = Wh2 @ relu(Wh1 @ g_h0[n] + bh1) + bh2
__global__ void k_head(const float* __restrict__ Wh1, const float* __restrict__ bh1,
                       const float* __restrict__ Wh2, const float* __restrict__ bh2,
                       float* __restrict__ out) {
    const float* h = (const float*)g_h0;
    __shared__ float w1[64 * 129];
    __shared__ float w2[256];
    __shared__ float hrow[128];
    __shared__ float mid[64];
    int t = threadIdx.x;  // 128 threads

    for (int idx = t; idx < 64 * 128; idx += 128) {
        int j = idx >> 7, k = idx & 127;
        w1[j * 129 + k] = Wh1[idx];
    }
    for (int idx = t; idx < 256; idx += 128) w2[idx] = Wh2[idx];
    __syncthreads();

    int base = blockIdx.x * NPB;
    for (int nn = 0; nn < NPB; nn++) {
        int node = base + nn;
        if (node >= NN) break;
        hrow[t] = h[node * 128 + t];
        __syncthreads();
        if (t < 64) {
            float s = bh1[t];
            const float* wr = &w1[t * 129];
#pragma unroll 8
            for (int k = 0; k < 128; k++) s += hrow[k] * wr[k];
            mid[t] = fmaxf(s, 0.f);
        }
        __syncthreads();
        if (t < 4) {
            float s = bh2[t];
#pragma unroll 8
            for (int k = 0; k < 64; k++) s += mid[k] * w2[t * 64 + k];
            out[node * 4 + t] = s;
        }
        __syncthreads();
    }
}

// ------------------------- launch -------------------------------------------
extern "C" void kernel_launch(void* const* d_in, const int* in_sizes, int n_in,
                              void* d_out, int out_size) {
    const float* x   = (const float*)d_in[0];
    const int*   ei  = (const int*)d_in[1];
    const float* Wl0 = (const float*)d_in[2];
    const float* bl0 = (const float*)d_in[3];
    const float* Wr0 = (const float*)d_in[4];
    const float* Wl1 = (const float*)d_in[5];
    const float* bl1 = (const float*)d_in[6];
    const float* Wr1 = (const float*)d_in[7];
    const float* Wl2 = (const float*)d_in[8];
    const float* bl2 = (const float*)d_in[9];
    const float* Wr2 = (const float*)d_in[10];
    const float* Wh1 = (const float*)d_in[11];
    const float* bh1 = (const float*)d_in[12];
    const float* Wh2 = (const float*)d_in[13];
    const float* bh2 = (const float*)d_in[14];
    const int* srcp = ei;
    const int* dstp = ei + EE;
    float* out = (float*)d_out;

    // CSR build (deterministic graph -> rebuilt identically every launch)
    k_zero_counts<<<(NN + 1 + 255) / 256, 256>>>();
    k_count<<<(EE + 255) / 256, 256>>>(dstp);
    k_scan<<<1, 1024>>>();
    k_fill<<<(EE + 255) / 256, 256>>>(srcp, dstp);

    int aggGrid = (NN * 32 + 255) / 256;
    int gemmGrid = (NN + BM - 1) / BM;

    // layer 0: x -> g_h0
    k_prep<<<(K2 * HH + 255) / 256, 256>>>(Wl0, Wr0);
    k_aggregate<<<aggGrid, 256>>>(x, 0);
    k_gemm<<<gemmGrid, 256>>>(bl0, 1);
    // layer 1: g_h0 -> g_h1
    k_prep<<<(K2 * HH + 255) / 256, 256>>>(Wl1, Wr1);
    k_aggregate<<<aggGrid, 256>>>(x, 1);
    k_gemm<<<gemmGrid, 256>>>(bl1, 2);
    // layer 2: g_h1 -> g_h0
    k_prep<<<(K2 * HH + 255) / 256, 256>>>(Wl2, Wr2);
    k_aggregate<<<aggGrid, 256>>>(x, 2);
    k_gemm<<<gemmGrid, 256>>>(bl2, 1);

    // head: g_h0 -> out
    k_head<<<(NN + NPB - 1) / NPB, 128>>>(Wh1, bh1, Wh2, bh2, out);
}

// round 5
// speedup vs baseline: 1.0703x; 1.0703x over previous
#include <cuda_runtime.h>

#define NN 50000
#define EE 800000
#define HH 128
#define N2 256
#define BM 128
#define BK 16

// ------------------------- device scratch (no allocations allowed) ----------
__device__ int   g_rowptr[NN + 1];
__device__ int   g_cursor[NN];
__device__ int   g_csr[EE];
__device__ float g_z[NN * N2];       // per-layer transformed [z_l | z_r]
__device__ float g_h[NN * HH];       // layer output (single buffer, safe by kernel order)
__device__ float g_wcatT[HH * N2];   // [k][jj]: jj<128 -> Wl[jj][k], else Wr[jj-128][k]
__device__ float g_w1T[HH * 64];     // Wh1 transposed k-major

// ------------------------- f32x2 helpers ------------------------------------
__device__ __forceinline__ unsigned long long pk2(float lo, float hi) {
    unsigned long long r;
    asm("mov.b64 %0, {%1, %2};" : "=l"(r) : "f"(lo), "f"(hi));
    return r;
}
__device__ __forceinline__ void upk2(unsigned long long v, float& lo, float& hi) {
    asm("mov.b64 {%0, %1}, %2;" : "=f"(lo), "=f"(hi) : "l"(v));
}
__device__ __forceinline__ void fma2(unsigned long long& d, unsigned long long a, unsigned long long b) {
    asm("fma.rn.f32x2 %0, %1, %2, %3;" : "=l"(d) : "l"(a), "l"(b), "l"(d));
}

// ------------------------- CSR build ----------------------------------------
__global__ void k_zero_counts() {
    int i = blockIdx.x * blockDim.x + threadIdx.x;
    if (i <= NN) g_rowptr[i] = 0;
}

__global__ void k_count(const int* __restrict__ dst) {
    int e = blockIdx.x * blockDim.x + threadIdx.x;
    if (e < EE) atomicAdd(&g_rowptr[dst[e]], 1);
}

__global__ void k_scan() {
    __shared__ int s[1024];
    int t = threadIdx.x;
    const int chunk = (NN + 1023) / 1024;
    int b = t * chunk;
    int e = b + chunk;
    if (e > NN) e = NN;
    int sum = 0;
    for (int i = b; i < e; i++) sum += g_rowptr[i];
    s[t] = sum;
    __syncthreads();
    for (int off = 1; off < 1024; off <<= 1) {
        int v = (t >= off) ? s[t - off] : 0;
        __syncthreads();
        s[t] += v;
        __syncthreads();
    }
    int run = (t == 0) ? 0 : s[t - 1];
    for (int i = b; i < e; i++) {
        int c = g_rowptr[i];
        g_rowptr[i] = run;
        g_cursor[i] = run;
        run += c;
    }
    if (t == 0) g_rowptr[NN] = EE;
}

__global__ void k_fill(const int* __restrict__ src, const int* __restrict__ dst) {
    int e = blockIdx.x * blockDim.x + threadIdx.x;
    if (e < EE) {
        int d = dst[e];
        int pos = atomicAdd(&g_cursor[d], 1);
        g_csr[pos] = src[e];
    }
}

// ------------------------- weight concat/transpose --------------------------
__global__ void k_prep(const float* __restrict__ Wl, const float* __restrict__ Wr) {
    int idx = blockIdx.x * blockDim.x + threadIdx.x;  // over 128*256
    if (idx < HH * N2) {
        int k = idx >> 8;
        int jj = idx & 255;
        g_wcatT[idx] = (jj < HH) ? Wl[jj * HH + k] : Wr[(jj - HH) * HH + k];
    }
}

__global__ void k_prep_head(const float* __restrict__ Wh1) {
    int idx = blockIdx.x * blockDim.x + threadIdx.x;  // over 128*64
    if (idx < HH * 64) {
        int k = idx >> 6;
        int j = idx & 63;
        g_w1T[idx] = Wh1[j * HH + k];
    }
}

// ------------------------- SGEMM: z = in @ [Wl|Wr]^T (f32x2) ----------------
// grid (ceil(NN/128), 2); blockIdx.y selects the 128-col half of wcatT.
__global__ void __launch_bounds__(256, 2) k_gemm(const float* __restrict__ xext, int src_sel) {
    const float* in = (src_sel == 0) ? xext : (const float*)g_h;
    __shared__ unsigned long long As2[BK][BM + 1];  // duplicated {a,a}
    __shared__ float Bs[BK][128];

    int tid = threadIdx.x;
    int blockRow = blockIdx.x * BM;
    int colBase = blockIdx.y * 128;
    const float4* in4 = (const float4*)in;
    const float4* w4 = (const float4*)g_wcatT;   // row k: 64 float4

    unsigned long long acc[8][4];
#pragma unroll
    for (int i = 0; i < 8; i++)
#pragma unroll
        for (int j = 0; j < 4; j++) acc[i][j] = 0ull;

    int tx = tid & 15, ty = tid >> 4;

    for (int k0 = 0; k0 < HH; k0 += BK) {
#pragma unroll
        for (int t = 0; t < 2; t++) {
            int idx = tid + t * 256;     // 0..511
            int row = idx >> 2;          // 0..127
            int k4 = idx & 3;
            int grow = blockRow + row;
            float4 v = make_float4(0.f, 0.f, 0.f, 0.f);
            if (grow < NN) v = in4[grow * 32 + (k0 >> 2) + k4];
            int kk = k4 * 4;
            As2[kk + 0][row] = pk2(v.x, v.x);
            As2[kk + 1][row] = pk2(v.y, v.y);
            As2[kk + 2][row] = pk2(v.z, v.z);
            As2[kk + 3][row] = pk2(v.w, v.w);
        }
#pragma unroll
        for (int t = 0; t < 2; t++) {
            int idx = tid + t * 256;
            int k = idx >> 5;            // 0..15
            int c4 = idx & 31;           // 0..31
            float4 v = w4[(k0 + k) * 64 + (colBase >> 2) + c4];
            *(float4*)&Bs[k][c4 * 4] = v;
        }
        __syncthreads();

#pragma unroll
        for (int kk = 0; kk < BK; kk++) {
            float4 b0 = *(const float4*)&Bs[kk][tx * 8];
            float4 b1 = *(const float4*)&Bs[kk][tx * 8 + 4];
            unsigned long long bb0 = pk2(b0.x, b0.y);
            unsigned long long bb1 = pk2(b0.z, b0.w);
            unsigned long long bb2 = pk2(b1.x, b1.y);
            unsigned long long bb3 = pk2(b1.z, b1.w);
#pragma unroll
            for (int i = 0; i < 8; i++) {
                unsigned long long aa = As2[kk][ty * 8 + i];
                fma2(acc[i][0], aa, bb0);
                fma2(acc[i][1], aa, bb1);
                fma2(acc[i][2], aa, bb2);
                fma2(acc[i][3], aa, bb3);
            }
        }
        __syncthreads();
    }

#pragma unroll
    for (int i = 0; i < 8; i++) {
        int grow = blockRow + ty * 8 + i;
        if (grow < NN) {
#pragma unroll
            for (int j4 = 0; j4 < 4; j4++) {
                int col = tx * 8 + j4 * 2;
                float lo, hi;
                upk2(acc[i][j4], lo, hi);
                float2 o; o.x = lo; o.y = hi;
                *(float2*)&g_z[grow * N2 + colBase + col] = o;
            }
        }
    }
}

// ------------------------- aggregate + epilogue ------------------------------
// h[n] = relu( mean_{nbr} z_l[nbr] + bl + z_r[n] )
__global__ void k_aggregate(const float* __restrict__ bl) {
    int gt = blockIdx.x * blockDim.x + threadIdx.x;
    int node = gt >> 5;
    int lane = gt & 31;
    if (node >= NN) return;
    int s0 = g_rowptr[node], s1 = g_rowptr[node + 1];
    const float4* z4 = (const float4*)g_z;     // row stride 64 float4
    float4 a0 = make_float4(0.f, 0.f, 0.f, 0.f);
    float4 a1 = a0;
    int i = s0;
    for (; i + 2 <= s1; i += 2) {
        int p = g_csr[i];
        int q = g_csr[i + 1];
        float4 v = z4[p * 64 + lane];
        float4 w = z4[q * 64 + lane];
        a0.x += v.x; a0.y += v.y; a0.z += v.z; a0.w += v.w;
        a1.x += w.x; a1.y += w.y; a1.z += w.z; a1.w += w.w;
    }
    if (i < s1) {
        int p = g_csr[i];
        float4 v = z4[p * 64 + lane];
        a0.x += v.x; a0.y += v.y; a0.z += v.z; a0.w += v.w;
    }
    float inv = 1.f / fmaxf((float)(s1 - s0), 1.f);
    float4 own = z4[node * 64 + 32 + lane];
    float4 b = ((const float4*)bl)[lane];
    float4 o;
    o.x = fmaxf((a0.x + a1.x) * inv + b.x + own.x, 0.f);
    o.y = fmaxf((a0.y + a1.y) * inv + b.y + own.y, 0.f);
    o.z = fmaxf((a0.z + a1.z) * inv + b.z + own.z, 0.f);
    o.w = fmaxf((a0.w + a1.w) * inv + b.w + own.w, 0.f);
    ((float4*)g_h)[node * 32 + lane] = o;
}

// ------------------------- fused head MLP (f32x2 GEMM) -----------------------
// out[n] = Wh2 @ relu(Wh1 @ g_h[n] + bh1) + bh2
// smem union: phase1 {As2 16x129 u64 | w1s 16x64 f32}, phase2 {mids 128x65 f32},
// w2/bh2 live beyond both regions.
#define HB_AS2_OFF   0
#define HB_W1S_OFF   16512
#define HB_MIDS_OFF  0
#define HB_W2_OFF    33280
#define HB_TOTAL     (33280 + 1040 + 16)

__global__ void __launch_bounds__(256, 2) k_head(const float* __restrict__ bh1,
                                                 const float* __restrict__ Wh2,
                                                 const float* __restrict__ bh2,
                                                 float* __restrict__ out) {
    __shared__ __align__(16) char sbuf[HB_TOTAL];
    unsigned long long* As2 = (unsigned long long*)(sbuf + HB_AS2_OFF);   // [16][129]
    float* w1s  = (float*)(sbuf + HB_W1S_OFF);                            // [16][64]
    float* mids = (float*)(sbuf + HB_MIDS_OFF);                           // [128][65]
    float* w2   = (float*)(sbuf + HB_W2_OFF);                             // [256] + bh2[4]

    int tid = threadIdx.x;
    int blockRow = blockIdx.x * BM;
    const float4* h4 = (const float4*)g_h;
    const float4* w1T4 = (const float4*)g_w1T;   // row k: 16 float4

    if (tid < 256) {
        w2[tid] = Wh2[tid];
        if (tid < 4) w2[256 + tid] = bh2[tid];
    }

    int tx = tid & 7;    // col group: cols tx*8 .. +7
    int ty = tid >> 3;   // row group: rows ty*4 .. +3

    unsigned long long acc[4][4];
#pragma unroll
    for (int i = 0; i < 4; i++)
#pragma unroll
        for (int j = 0; j < 4; j++) acc[i][j] = 0ull;

    for (int k0 = 0; k0 < HH; k0 += BK) {
#pragma unroll
        for (int t = 0; t < 2; t++) {
            int idx = tid + t * 256;
            int row = idx >> 2;
            int k4 = idx & 3;
            int grow = blockRow + row;
            float4 v = make_float4(0.f, 0.f, 0.f, 0.f);
            if (grow < NN) v = h4[grow * 32 + (k0 >> 2) + k4];
            int kk = k4 * 4;
            As2[(kk + 0) * 129 + row] = pk2(v.x, v.x);
            As2[(kk + 1) * 129 + row] = pk2(v.y, v.y);
            As2[(kk + 2) * 129 + row] = pk2(v.z, v.z);
            As2[(kk + 3) * 129 + row] = pk2(v.w, v.w);
        }
        {
            int k = tid >> 4;            // 0..15
            int c4 = tid & 15;           // 0..15
            float4 v = w1T4[(k0 + k) * 16 + c4];
            *(float4*)&w1s[k * 64 + c4 * 4] = v;
        }
        __syncthreads();

#pragma unroll
        for (int kk = 0; kk < BK; kk++) {
            float4 b0 = *(const float4*)&w1s[kk * 64 + tx * 8];
            float4 b1 = *(const float4*)&w1s[kk * 64 + tx * 8 + 4];
            unsigned long long bb0 = pk2(b0.x, b0.y);
            unsigned long long bb1 = pk2(b0.z, b0.w);
            unsigned long long bb2 = pk2(b1.x, b1.y);
            unsigned long long bb3 = pk2(b1.z, b1.w);
#pragma unroll
            for (int i = 0; i < 4; i++) {
                unsigned long long aa = As2[kk * 129 + ty * 4 + i];
                fma2(acc[i][0], aa, bb0);
                fma2(acc[i][1], aa, bb1);
                fma2(acc[i][2], aa, bb2);
                fma2(acc[i][3], aa, bb3);
            }
        }
        __syncthreads();
    }

    // epilogue phase1: mids[row][col] = relu(acc + bh1[col])  (overlays As2/w1s)
#pragma unroll
    for (int i = 0; i < 4; i++) {
        int row = ty * 4 + i;
#pragma unroll
        for (int j4 = 0; j4 < 4; j4++) {
            int col = tx * 8 + j4 * 2;
            float lo, hi;
            upk2(acc[i][j4], lo, hi);
            mids[row * 65 + col]     = fmaxf(lo + bh1[col], 0.f);
            mids[row * 65 + col + 1] = fmaxf(hi + bh1[col + 1], 0.f);
        }
    }
    __syncthreads();

    // phase2: out[row][c] = dot(mids[row], Wh2[c]) + bh2[c], 2 outputs/thread
#pragma unroll
    for (int t2 = 0; t2 < 2; t2++) {
        int oidx = tid + t2 * 256;       // 0..511
        int row = oidx >> 2;
        int c = oidx & 3;
        int node = blockRow + row;
        if (node < NN) {
            float s = w2[256 + c];
            const float* mr = &mids[row * 65];
            const float* wr = &w2[c * 64];
#pragma unroll 8
            for (int k = 0; k < 64; k++) s += mr[k] * wr[k];
            out[node * 4 + c] = s;
        }
    }
}

// ------------------------- launch -------------------------------------------
extern "C" void kernel_launch(void* const* d_in, const int* in_sizes, int n_in,
                              void* d_out, int out_size) {
    const float* x   = (const float*)d_in[0];
    const int*   ei  = (const int*)d_in[1];
    const float* Wl0 = (const float*)d_in[2];
    const float* bl0 = (const float*)d_in[3];
    const float* Wr0 = (const float*)d_in[4];
    const float* Wl1 = (const float*)d_in[5];
    const float* bl1 = (const float*)d_in[6];
    const float* Wr1 = (const float*)d_in[7];
    const float* Wl2 = (const float*)d_in[8];
    const float* bl2 = (const float*)d_in[9];
    const float* Wr2 = (const float*)d_in[10];
    const float* Wh1 = (const float*)d_in[11];
    const float* bh1 = (const float*)d_in[12];
    const float* Wh2 = (const float*)d_in[13];
    const float* bh2 = (const float*)d_in[14];
    const int* srcp = ei;
    const int* dstp = ei + EE;
    float* out = (float*)d_out;

    // CSR build (graph fixed across layers)
    k_zero_counts<<<(NN + 1 + 255) / 256, 256>>>();
    k_count<<<(EE + 255) / 256, 256>>>(dstp);
    k_scan<<<1, 1024>>>();
    k_fill<<<(EE + 255) / 256, 256>>>(srcp, dstp);

    dim3 gemmGrid((NN + BM - 1) / BM, 2);
    int aggGrid = (NN * 32 + 255) / 256;
    int prepGrid = (HH * N2 + 255) / 256;

    // layer 0: x -> z -> h
    k_prep<<<prepGrid, 256>>>(Wl0, Wr0);
    k_gemm<<<gemmGrid, 256>>>(x, 0);
    k_aggregate<<<aggGrid, 256>>>(bl0);
    // layer 1: h -> z -> h
    k_prep<<<prepGrid, 256>>>(Wl1, Wr1);
    k_gemm<<<gemmGrid, 256>>>(x, 1);
    k_aggregate<<<aggGrid, 256>>>(bl1);
    // layer 2: h -> z -> h
    k_prep<<<prepGrid, 256>>>(Wl2, Wr2);
    k_gemm<<<gemmGrid, 256>>>(x, 1);
    k_aggregate<<<aggGrid, 256>>>(bl2);

    // head: h -> out
    k_prep_head<<<(HH * 64 + 255) / 256, 256>>>(Wh1);
    k_head<<<(NN + BM - 1) / BM, 256>>>(bh1, Wh2, bh2, out);
}